// round 9
// baseline (speedup 1.0000x reference)
#include <cuda_runtime.h>
#include <math.h>

#define STEPS 2048
#define BATCH 512
#define NBLK  128            // one CTA per SM, one wave
#define THREADS 512          // 2 groups x 256 threads, 2 samples each

typedef unsigned long long u64;

__device__ float g_baseflow[BATCH];

// ---------------------------------------------------------------------------
__device__ __forceinline__ u64 pack2(float lo, float hi) {
    u64 r; asm("mov.b64 %0, {%1, %2};" : "=l"(r) : "f"(lo), "f"(hi)); return r;
}
__device__ __forceinline__ void fma2(u64& acc, u64 a, u64 b) {
    asm("fma.rn.f32x2 %0, %1, %2, %0;" : "+l"(acc) : "l"(a), "l"(b));
}
__device__ __forceinline__ float fast_sigmoid(float v) {
    return __fdividef(1.0f, 1.0f + __expf(-v));
}

// ---------------------------------------------------------------------------
// Kernel 1: per-batch-element 25th percentile of flow (bitonic sort)
// ---------------------------------------------------------------------------
__global__ void baseflow_kernel(const float* __restrict__ hyd) {
    __shared__ float v[STEPS];
    const int b = blockIdx.x;
    const int tid = threadIdx.x;
    for (int t = tid; t < STEPS; t += blockDim.x)
        v[t] = hyd[(t * BATCH + b) * 17];
    __syncthreads();
    for (int k = 2; k <= STEPS; k <<= 1) {
        for (int j = k >> 1; j > 0; j >>= 1) {
            for (int i = tid; i < STEPS; i += blockDim.x) {
                int l = i ^ j;
                if (l > i) {
                    float a = v[i], c = v[l];
                    bool up = ((i & k) == 0);
                    if ((a > c) == up) { v[i] = c; v[l] = a; }
                }
            }
            __syncthreads();
        }
    }
    if (tid == 0)
        g_baseflow[b] = 0.25f * v[511] + 0.75f * v[512];   // pos = 511.75
}

// ---------------------------------------------------------------------------
// SMEM: shared weights + per-group private buffers (~80 KB total)
// ---------------------------------------------------------------------------
struct __align__(16) GroupBuf {
    float xin[16 * 2];       // staged x_{t+1} [i][s]
    float l0p[128 * 2];      // layer0-x partial incl b0 [j][s]
    float hA[128 * 2];       // layer0 out [j][s]
    float hB[128 * 2];       // layer1 out
    float part1[4][128][2];  // layer1 partials [q][j][s]
    float part2[2][96][2];   // layer2 partials [q][j][s]
    float outg[2][80];       // sigmoided gates [s][col]
    float st[2 * 8];         // stores broadcast
    float bflow_s[2];
    float pad[2];
};

struct __align__(16) Smem {
    float wct[128 * 96];     // 48KB combined [W_in;W_out]^T [k][j] (j<89 valid)
    float w0t[16 * 128];     // W0 x-part transposed [i][j]
    float w0sp[8 * 128];     // 0.01 * W0 stores-part [k][j]
    float b0s[128];
    float b1s[128];
    float bcs[96];
    GroupBuf grp[2];
};

// ---------------------------------------------------------------------------
// 512 threads = 16 warps = 2 independent groups of 8 warps.
// Group g handles samples blk*4 + 2g + {0,1}; groups synchronize ONLY via
// named barrier (g+1). Group 1 is phase-shifted ~half a step so its fat
// matvec stages overlap group 0's narrow epilogue (and vice versa).
// Within a group (gtid = tid & 255):
//   S1: layer1 partials; thread owns units (u6, u6+64), k-slice q4 (W1 regs)
//   S2: combine1 -> hB ; stage x_{t+1}
//   S3: layer2 partials (gtid<178, SMEM weights) || l0x(t+1) (warps 6-7)
//   S4: epilogue on group warps 0,1 (one sample each)
//   S5: hA(t+1) finish (all 256)
// ---------------------------------------------------------------------------
__global__ void __launch_bounds__(THREADS, 1)
hyd_kernel(const float* __restrict__ hyd,
           const float* __restrict__ W0, const float* __restrict__ b0,
           const float* __restrict__ W1, const float* __restrict__ b1,
           const float* __restrict__ Wi, const float* __restrict__ bi,
           const float* __restrict__ Wo, const float* __restrict__ bo,
           float* __restrict__ out)
{
    extern __shared__ char raw[];
    Smem& S = *(Smem*)raw;
    const int tid   = threadIdx.x;
    const int g     = tid >> 8;          // group 0 / 1
    const int gtid  = tid & 255;
    const int lane  = tid & 31;
    const int gwarp = gtid >> 5;         // warp within group: 0..7
    const int u6    = gtid & 63;
    const int q4    = gtid >> 6;         // 0..3
    const int blk   = blockIdx.x;
    GroupBuf& G = S.grp[g];

    #define BARG() asm volatile("bar.sync %0, 256;" :: "r"(g + 1) : "memory")

    // ---- register-resident W1 slices: units u6, u6+64; k in [32*q4, +32) ----
    float w1a[32], w1b[32];
    #pragma unroll
    for (int k = 0; k < 32; k++) {
        w1a[k] = W1[u6 * 128 + q4 * 32 + k];
        w1b[k] = W1[(u6 + 64) * 128 + q4 * 32 + k];
    }

    // ---- SMEM init (block-wide, once) ----
    for (int idx = tid; idx < 128 * 96; idx += THREADS) {
        int k = idx / 96, j = idx % 96;
        float v = 0.f;
        if (j < 9)       v = Wi[j * 128 + k];
        else if (j < 89) v = Wo[(j - 9) * 128 + k];
        S.wct[idx] = v;
    }
    for (int idx = tid; idx < 16 * 128; idx += THREADS) {
        int i = idx >> 7, jj = idx & 127;
        S.w0t[idx] = W0[jj * 24 + i];
    }
    for (int idx = tid; idx < 8 * 128; idx += THREADS) {
        int k = idx >> 7, jj = idx & 127;
        S.w0sp[idx] = 0.01f * W0[jj * 24 + 16 + k];
    }
    if (tid < 128) { S.b0s[tid] = b0[tid]; S.b1s[tid] = b1[tid]; }
    if (tid < 96)  S.bcs[tid] = (tid < 9) ? bi[tid] : (tid < 89 ? bo[tid - 9] : 0.f);
    if (gtid < 16) G.st[gtid] = ((gtid & 7) == 1) ? 1.0f : 0.0f;
    if (gtid < 2)  G.bflow_s[gtid] = g_baseflow[blk * 4 + g * 2 + gtid];

    // per-warp roles within the group
    const int bsample = blk * 4 + g * 2 + gwarp;          // warps 0,1: epilogue
    const int xsample = blk * 4 + g * 2 + (gwarp - 2);    // warps 2,3: x prefetch
    float rain_cur = 0.f, rain_next = 0.f, xreg = 0.f;

    if (gwarp < 2 && lane == 0)
        rain_cur = hyd[bsample * 17 + 1];
    if (gwarp >= 2 && gwarp < 4 && lane < 16)
        G.xin[lane * 2 + (gwarp - 2)] = hyd[xsample * 17 + 1 + lane];
    __syncthreads();   // last block-wide sync: weights + xin visible

    // ---- bootstrap (idempotent); group 1 repeats it to phase-shift ----
    const int reps = (g == 0) ? 1 : 7;
    for (int r = 0; r < reps; r++) {
        {   // l0p(0)
            int jj = gtid >> 1, s = gtid & 1;
            float v = S.b0s[jj];
            #pragma unroll
            for (int i = 0; i < 16; i++)
                v = fmaf(S.w0t[i * 128 + jj], G.xin[i * 2 + s], v);
            G.l0p[jj * 2 + s] = v;
        }
        BARG();
        {   // hA(0)
            int jj = gtid >> 1, s = gtid & 1;
            float v = G.l0p[jj * 2 + s];
            #pragma unroll
            for (int k = 0; k < 8; k++)
                v = fmaf(S.w0sp[k * 128 + jj], G.st[s * 8 + k], v);
            G.hA[jj * 2 + s] = fmaxf(v, 0.f);
        }
        BARG();
    }

    // persistent stores in lane 0 of group warps 0,1
    float sv[8];
    #pragma unroll
    for (int k = 0; k < 8; k++) sv[k] = (k == 1) ? 1.0f : 0.0f;

    // layer2 role
    const int j2 = (gtid < 178) ? (gtid % 89) : 0;
    const int q2 = (gtid < 178) ? (gtid / 89) : 0;

    for (int t = 0; t < STEPS; t++) {
        // ======== S1: layer1 partials ========
        {
            float ba  = (q4 == 0) ? S.b1s[u6] : 0.f;
            float bb_ = (q4 == 0) ? S.b1s[u6 + 64] : 0.f;
            u64 aa = pack2(ba, ba), ab = pack2(bb_, bb_);
            const float* hp = &G.hA[q4 * 32 * 2];
            #pragma unroll
            for (int k = 0; k < 32; k++) {
                u64 h = *(const u64*)&hp[k * 2];
                fma2(aa, h, pack2(w1a[k], w1a[k]));
                fma2(ab, h, pack2(w1b[k], w1b[k]));
            }
            *(u64*)&G.part1[q4][u6][0]      = aa;
            *(u64*)&G.part1[q4][u6 + 64][0] = ab;
        }
        // prefetch x_{t+1} / rain_{t+1}
        if (t + 1 < STEPS) {
            if (gwarp < 2 && lane == 0)
                rain_next = hyd[((t + 1) * BATCH + bsample) * 17 + 1];
            if (gwarp >= 2 && gwarp < 4 && lane < 16)
                xreg = hyd[((t + 1) * BATCH + xsample) * 17 + 1 + lane];
        }
        BARG();

        // ======== S2: combine1 -> hB ; stage x_{t+1} ========
        {
            int jj = gtid >> 1, s = gtid & 1;
            float v = G.part1[0][jj][s] + G.part1[1][jj][s]
                    + G.part1[2][jj][s] + G.part1[3][jj][s];
            G.hB[jj * 2 + s] = fmaxf(v, 0.f);
        }
        if (gwarp >= 2 && gwarp < 4 && lane < 16)
            G.xin[lane * 2 + (gwarp - 2)] = xreg;
        BARG();

        // ======== S3: layer2 (gtid<178) || l0x(t+1) (warps 6-7) ========
        if (gwarp >= 6) {
            int u = gtid - 192;
            float b0a = S.b0s[u], b0b = S.b0s[u + 64];
            u64 aa = pack2(b0a, b0a), ab = pack2(b0b, b0b);
            #pragma unroll
            for (int i = 0; i < 16; i++) {
                u64 h = *(const u64*)&G.xin[i * 2];
                fma2(aa, h, pack2(S.w0t[i * 128 + u], S.w0t[i * 128 + u]));
                fma2(ab, h, pack2(S.w0t[i * 128 + u + 64], S.w0t[i * 128 + u + 64]));
            }
            *(u64*)&G.l0p[u * 2]        = aa;
            *(u64*)&G.l0p[(u + 64) * 2] = ab;
        } else if (gtid < 178) {
            float bj = (q2 == 0) ? S.bcs[j2] : 0.f;
            u64 acc = pack2(bj, bj);
            const float* hp = &G.hB[q2 * 64 * 2];
            const float* wp = &S.wct[q2 * 64 * 96 + j2];
            #pragma unroll
            for (int k = 0; k < 64; k++) {
                float w = wp[k * 96];
                u64 h = *(const u64*)&hp[k * 2];
                fma2(acc, h, pack2(w, w));
            }
            *(u64*)&G.part2[q2][j2][0] = acc;
        }
        BARG();

        // ======== S4: epilogue (group warps 0,1; warp s = sample s) ========
        if (gwarp < 2) {
            const int s = gwarp;
            float v0 = G.part2[0][lane][s] + G.part2[1][lane][s];
            int j1 = lane + 32, jx = lane + 64;
            float v1 = G.part2[0][j1][s] + G.part2[1][j1][s];
            float v2 = 0.f;
            if (lane < 25)
                v2 = G.part2[0][jx][s] + G.part2[1][jx][s];

            // sigmoids spread across lanes
            if (lane >= 9) G.outg[s][lane - 9] = fast_sigmoid(v0);
            G.outg[s][lane + 23] = fast_sigmoid(v1);
            if (lane < 25) G.outg[s][lane + 55] = fast_sigmoid(v2);

            // gather 9 logits
            float lg[9];
            #pragma unroll
            for (int k = 0; k < 9; k++)
                lg[k] = __shfl_sync(0xffffffffu, v0, k);
            __syncwarp();

            if (lane == 0) {
                // softmax (tree max/sum)
                float m01 = fmaxf(lg[0], lg[1]), m23 = fmaxf(lg[2], lg[3]);
                float m45 = fmaxf(lg[4], lg[5]), m67 = fmaxf(lg[6], lg[7]);
                float m = fmaxf(fmaxf(fmaxf(m01, m23), fmaxf(m45, m67)), lg[8]);
                float e[9];
                #pragma unroll
                for (int k = 0; k < 9; k++) e[k] = __expf(lg[k] - m);
                float s01 = e[0] + e[1], s23 = e[2] + e[3];
                float s45 = e[4] + e[5], s67 = e[6] + e[7];
                float ssum = ((s01 + s23) + (s45 + s67)) + e[8];
                float r2 = __fdividef(rain_cur, ssum);
                #pragma unroll
                for (int k = 0; k < 8; k++) sv[k] += e[k + 1] * r2;

                const float* bb = G.outg[s];
                #pragma unroll
                for (int d = 0; d < 8; d++) {
                    float4 bv0 = *(const float4*)&bb[d * 8];
                    float4 bv1 = *(const float4*)&bb[d * 8 + 4];
                    float fb0 = bv0.x * sv[0], fb1 = bv0.y * sv[1];
                    float fb2 = bv0.z * sv[2], fb3 = bv0.w * sv[3];
                    float fb4 = bv1.x * sv[4], fb5 = bv1.y * sv[5];
                    float fb6 = bv1.z * sv[6], fb7 = bv1.w * sv[7];
                    float fsum = ((fb0 + fb1) + (fb2 + fb3))
                               + ((fb4 + fb5) + (fb6 + fb7));
                    sv[0] -= fb0; sv[1] -= fb1; sv[2] -= fb2; sv[3] -= fb3;
                    sv[4] -= fb4; sv[5] -= fb5; sv[6] -= fb6; sv[7] -= fb7;
                    sv[d] += fsum;
                }
                {   // escape
                    float4 e0 = *(const float4*)&bb[64];
                    float4 e1 = *(const float4*)&bb[68];
                    sv[0] -= e0.x * sv[0]; sv[1] -= e0.y * sv[1];
                    sv[2] -= e0.z * sv[2]; sv[3] -= e0.w * sv[3];
                    sv[4] -= e1.x * sv[4]; sv[5] -= e1.y * sv[5];
                    sv[6] -= e1.z * sv[6]; sv[7] -= e1.w * sv[7];
                }
                {   // flow
                    float4 f0 = *(const float4*)&bb[72];
                    float4 f1 = *(const float4*)&bb[76];
                    float fd0 = f0.x * sv[0], fd1 = f0.y * sv[1];
                    float fd2 = f0.z * sv[2], fd3 = f0.w * sv[3];
                    float fd4 = f1.x * sv[4], fd5 = f1.y * sv[5];
                    float fd6 = f1.z * sv[6], fd7 = f1.w * sv[7];
                    float flow = ((fd0 + fd1) + (fd2 + fd3))
                               + ((fd4 + fd5) + (fd6 + fd7));
                    sv[0] -= fd0; sv[1] -= fd1; sv[2] -= fd2; sv[3] -= fd3;
                    sv[4] -= fd4; sv[5] -= fd5; sv[6] -= fd6; sv[7] -= fd7;
                    out[t * BATCH + bsample] = flow;
                    if (t == 0)
                        sv[2] = G.bflow_s[s] / fmaxf(f0.z, 1e-5f);  // b_flow[SLOW]
                }
                #pragma unroll
                for (int k = 0; k < 8; k++) G.st[s * 8 + k] = sv[k];
                rain_cur = rain_next;
            }
        }
        BARG();

        // ======== S5: hA(t+1) finish (all 256, one (j,s) each) ========
        {
            int jj = gtid >> 1, s = gtid & 1;
            float v = G.l0p[jj * 2 + s];
            #pragma unroll
            for (int k = 0; k < 8; k++)
                v = fmaf(S.w0sp[k * 128 + jj], G.st[s * 8 + k], v);
            G.hA[jj * 2 + s] = fmaxf(v, 0.f);
        }
        BARG();
    }
    #undef BARG
}

// ---------------------------------------------------------------------------
// Harness entry.  Inputs: hyd_input, W0, b0, W1, b1, W_in, b_in, W_out, b_out
// ---------------------------------------------------------------------------
extern "C" void kernel_launch(void* const* d_in, const int* in_sizes, int n_in,
                              void* d_out, int out_size) {
    const float* hyd = (const float*)d_in[0];
    const float* W0  = (const float*)d_in[1];
    const float* b0  = (const float*)d_in[2];
    const float* W1  = (const float*)d_in[3];
    const float* b1  = (const float*)d_in[4];
    const float* Wi  = (const float*)d_in[5];
    const float* bi  = (const float*)d_in[6];
    const float* Wo  = (const float*)d_in[7];
    const float* bo  = (const float*)d_in[8];
    float* out = (float*)d_out;

    cudaFuncSetAttribute(hyd_kernel,
                         cudaFuncAttributeMaxDynamicSharedMemorySize,
                         (int)sizeof(Smem));

    baseflow_kernel<<<BATCH, 1024>>>(hyd);
    hyd_kernel<<<NBLK, THREADS, sizeof(Smem)>>>(hyd, W0, b0, W1, b1, Wi, bi, Wo, bo, out);
}

// round 10
// speedup vs baseline: 1.1450x; 1.1450x over previous
#include <cuda_runtime.h>
#include <math.h>

#define STEPS 2048
#define BATCH 512
#define NBLK  128
#define THREADS 512

typedef unsigned long long u64;

__device__ float g_baseflow[BATCH];

// ---------------------------------------------------------------------------
__device__ __forceinline__ u64 pack2(float lo, float hi) {
    u64 r; asm("mov.b64 %0, {%1, %2};" : "=l"(r) : "f"(lo), "f"(hi)); return r;
}
__device__ __forceinline__ void unpack2(u64 v, float& lo, float& hi) {
    asm("mov.b64 {%0, %1}, %2;" : "=f"(lo), "=f"(hi) : "l"(v));
}
__device__ __forceinline__ void fma2(u64& acc, u64 a, u64 b) {
    asm("fma.rn.f32x2 %0, %1, %2, %0;" : "+l"(acc) : "l"(a), "l"(b));
}
__device__ __forceinline__ u64 add2(u64 a, u64 b) {
    u64 r; asm("add.rn.f32x2 %0, %1, %2;" : "=l"(r) : "l"(a), "l"(b)); return r;
}
__device__ __forceinline__ float fast_sigmoid(float v) {
    return __fdividef(1.0f, 1.0f + __expf(-v));
}

// ---------------------------------------------------------------------------
// Kernel 1: per-batch-element 25th percentile of flow (bitonic sort)
// ---------------------------------------------------------------------------
__global__ void baseflow_kernel(const float* __restrict__ hyd) {
    __shared__ float v[STEPS];
    const int b = blockIdx.x;
    const int tid = threadIdx.x;
    for (int t = tid; t < STEPS; t += blockDim.x)
        v[t] = hyd[(t * BATCH + b) * 17];
    __syncthreads();
    for (int k = 2; k <= STEPS; k <<= 1) {
        for (int j = k >> 1; j > 0; j >>= 1) {
            for (int i = tid; i < STEPS; i += blockDim.x) {
                int l = i ^ j;
                if (l > i) {
                    float a = v[i], c = v[l];
                    bool up = ((i & k) == 0);
                    if ((a > c) == up) { v[i] = c; v[l] = a; }
                }
            }
            __syncthreads();
        }
    }
    if (tid == 0)
        g_baseflow[b] = 0.25f * v[511] + 0.75f * v[512];   // pos = 511.75
}

// ---------------------------------------------------------------------------
// SMEM (~63 KB, dynamic)
// ---------------------------------------------------------------------------
struct __align__(16) Smem {
    float part1[16 * 512];   // 32KB: [q][u][ug][s] flat = q*512+u*128+ug*4+s
    float part2[16 * 384];   // 24KB: [q][u][g][s]  flat = q*384+u*96 +g*4 +s
    float hA[512];           // [k][s]
    float hB[512];           // [k][s]
    float l0p[512];          // [j][s]
    float xin[64];           // [i][s]
    float outg[4 * 80];      // [s][col]
    float lgt[48];           // [s*12 + j], j<9
    float st[32];            // [s][k]
    float bflow_s[4];
};

// ---------------------------------------------------------------------------
// 512 threads = 16 warps, 4 samples, one CTA/SM.
// S1: layer1, thread = (ug=lane: units 4*lane..+3) x (slice=warp: k 8*w..+8).
//     One broadcast LDS.128 per k feeds 8 FFMA2 (16 MACs).
// S2: combine1 -> hB (warps 0-7, f32x2 sample pairs); warps 8-11 stage xin.
// S3: layer2 partials (384 thr, units padded to 96, same U=4 blocking)
//     || warps 12-15: l0x(t+1) from register weights.
// S4: combine2 + sigmoid (192 thr, f32x2).
// S5: epilogue warps 0-3 (scalar softmax + serial tail + stores publish).
// S6: hA(t+1) = relu(l0p + W0s_regs . st)  (all 512).
// ---------------------------------------------------------------------------
__global__ void __launch_bounds__(THREADS, 1)
hyd_kernel(const float* __restrict__ hyd,
           const float* __restrict__ W0, const float* __restrict__ b0,
           const float* __restrict__ W1, const float* __restrict__ b1,
           const float* __restrict__ Wi, const float* __restrict__ bi,
           const float* __restrict__ Wo, const float* __restrict__ bo,
           float* __restrict__ out)
{
    extern __shared__ char raw[];
    Smem& S = *(Smem*)raw;
    const int tid  = threadIdx.x;
    const int lane = tid & 31;
    const int warp = tid >> 5;
    const int blk  = blockIdx.x;

    // ===== per-thread register preloads =====
    // S1: units 4*lane..4*lane+3, k in [8*warp, 8*warp+8)
    float w1r[4][8], b1R[4];
    #pragma unroll
    for (int u = 0; u < 4; u++) {
        int jj = 4 * lane + u;
        b1R[u] = b1[jj];
        #pragma unroll
        for (int k = 0; k < 8; k++)
            w1r[u][k] = W1[jj * 128 + 8 * warp + k];
    }
    // S3 layer2 role (tid<384): slice sl2 = tid/24, group g2 = tid%24
    const int sl2 = tid / 24;            // 0..15 for tid<384
    const int g2  = tid - sl2 * 24;
    float wc2[4][8], bc2R[4];
    if (tid < 384) {
        #pragma unroll
        for (int u = 0; u < 4; u++) {
            int jj = 4 * g2 + u;
            bc2R[u] = (jj < 9) ? bi[jj] : (jj < 89 ? bo[jj - 9] : 0.f);
            #pragma unroll
            for (int k = 0; k < 8; k++) {
                int kk = 8 * sl2 + k;
                wc2[u][k] = (jj < 9)  ? Wi[jj * 128 + kk]
                          : (jj < 89) ? Wo[(jj - 9) * 128 + kk] : 0.f;
            }
        }
    }
    // S3 l0x role (warps 12-15): unit j = tid-384
    float w0tR[16], b0R = 0.f;
    if (warp >= 12) {
        int jj = tid - 384;
        b0R = b0[jj];
        #pragma unroll
        for (int i = 0; i < 16; i++) w0tR[i] = W0[jj * 24 + i];
    }
    // S6 role (all): unit j6 = tid>>2
    float w0spR[8];
    {
        int jj = tid >> 2;
        #pragma unroll
        for (int k = 0; k < 8; k++) w0spR[k] = 0.01f * W0[jj * 24 + 16 + k];
    }

    // per-warp roles
    const int bsample = blk * 4 + warp;          // warps 0-3: epilogue sample
    const int xsample = blk * 4 + (warp - 8);    // warps 8-11: x prefetch
    float rain_cur = 0.f, rain_next = 0.f, xreg = 0.f;

    if (warp < 4 && lane == 0) rain_cur = hyd[bsample * 17 + 1];
    if (warp < 4 && lane < 4)  S.bflow_s[lane] = g_baseflow[blk * 4 + lane];
    if (warp >= 8 && warp < 12 && lane < 16)
        S.xin[lane * 4 + (warp - 8)] = hyd[xsample * 17 + 1 + lane];
    if (tid < 32) S.st[tid] = ((tid & 7) == 1) ? 1.0f : 0.0f;
    __syncthreads();

    // ===== bootstrap: l0p(0), hA(0) =====
    if (warp >= 12) {
        int jj = tid - 384;
        u64 a01 = pack2(b0R, b0R), a23 = a01;
        #pragma unroll
        for (int i = 0; i < 16; i++) {
            ulonglong2 h = *(const ulonglong2*)&S.xin[i * 4];
            u64 wd = pack2(w0tR[i], w0tR[i]);
            fma2(a01, h.x, wd); fma2(a23, h.y, wd);
        }
        ulonglong2 pv; pv.x = a01; pv.y = a23;
        *(ulonglong2*)&S.l0p[jj * 4] = pv;
    }
    __syncthreads();
    {
        int jj = tid >> 2, s = tid & 3;
        float4 s0 = *(const float4*)&S.st[s * 8];
        float4 s1 = *(const float4*)&S.st[s * 8 + 4];
        float v = S.l0p[jj * 4 + s];
        v = fmaf(w0spR[0], s0.x, v); v = fmaf(w0spR[1], s0.y, v);
        v = fmaf(w0spR[2], s0.z, v); v = fmaf(w0spR[3], s0.w, v);
        v = fmaf(w0spR[4], s1.x, v); v = fmaf(w0spR[5], s1.y, v);
        v = fmaf(w0spR[6], s1.z, v); v = fmaf(w0spR[7], s1.w, v);
        S.hA[jj * 4 + s] = fmaxf(v, 0.f);
    }
    __syncthreads();

    // persistent stores in lane 0 of warps 0-3
    float sv[8];
    #pragma unroll
    for (int k = 0; k < 8; k++) sv[k] = (k == 1) ? 1.0f : 0.0f;

    for (int t = 0; t < STEPS; t++) {
        // ======== S1: layer1 partials ========
        {
            u64 acc[4][2];
            #pragma unroll
            for (int u = 0; u < 4; u++) {
                float b = (warp == 0) ? b1R[u] : 0.f;
                acc[u][0] = pack2(b, b); acc[u][1] = acc[u][0];
            }
            const float* hp = &S.hA[warp * 32];
            #pragma unroll
            for (int k = 0; k < 8; k++) {
                ulonglong2 h = *(const ulonglong2*)&hp[k * 4];   // broadcast
                #pragma unroll
                for (int u = 0; u < 4; u++) {
                    u64 wd = pack2(w1r[u][k], w1r[u][k]);
                    fma2(acc[u][0], h.x, wd);
                    fma2(acc[u][1], h.y, wd);
                }
            }
            #pragma unroll
            for (int u = 0; u < 4; u++) {
                ulonglong2 pv; pv.x = acc[u][0]; pv.y = acc[u][1];
                *(ulonglong2*)&S.part1[warp * 512 + u * 128 + lane * 4] = pv;
            }
        }
        if (t + 1 < STEPS) {
            if (warp < 4 && lane == 0)
                rain_next = hyd[((t + 1) * BATCH + bsample) * 17 + 1];
            if (warp >= 8 && warp < 12 && lane < 16)
                xreg = hyd[((t + 1) * BATCH + xsample) * 17 + 1 + lane];
        }
        __syncthreads();

        // ======== S2: combine1 -> hB (warps 0-7) ; stage xin (8-11) ========
        if (warp < 8) {
            int u  = warp & 3;
            int g  = (warp >> 2) * 16 + (lane >> 1);
            int sp = lane & 1;
            int base = u * 128 + g * 4 + 2 * sp;
            u64 a = *(const u64*)&S.part1[base];
            #pragma unroll
            for (int q = 1; q < 16; q++)
                a = add2(a, *(const u64*)&S.part1[q * 512 + base]);
            float f0, f1; unpack2(a, f0, f1);
            u64 hv = pack2(fmaxf(f0, 0.f), fmaxf(f1, 0.f));
            int jj = 4 * g + u;
            *(u64*)&S.hB[jj * 4 + 2 * sp] = hv;
        } else if (warp < 12 && lane < 16) {
            S.xin[lane * 4 + (warp - 8)] = xreg;
        }
        __syncthreads();

        // ======== S3: layer2 partials (tid<384) || l0x (warps 12-15) ======
        if (warp >= 12) {
            int jj = tid - 384;
            u64 a01 = pack2(b0R, b0R), a23 = a01;
            #pragma unroll
            for (int i = 0; i < 16; i++) {
                ulonglong2 h = *(const ulonglong2*)&S.xin[i * 4];
                u64 wd = pack2(w0tR[i], w0tR[i]);
                fma2(a01, h.x, wd); fma2(a23, h.y, wd);
            }
            ulonglong2 pv; pv.x = a01; pv.y = a23;
            *(ulonglong2*)&S.l0p[jj * 4] = pv;
        } else {
            u64 acc[4][2];
            #pragma unroll
            for (int u = 0; u < 4; u++) {
                float b = (sl2 == 0) ? bc2R[u] : 0.f;
                acc[u][0] = pack2(b, b); acc[u][1] = acc[u][0];
            }
            const float* hp = &S.hB[sl2 * 32];
            #pragma unroll
            for (int k = 0; k < 8; k++) {
                ulonglong2 h = *(const ulonglong2*)&hp[k * 4];
                #pragma unroll
                for (int u = 0; u < 4; u++) {
                    u64 wd = pack2(wc2[u][k], wc2[u][k]);
                    fma2(acc[u][0], h.x, wd);
                    fma2(acc[u][1], h.y, wd);
                }
            }
            #pragma unroll
            for (int u = 0; u < 4; u++) {
                ulonglong2 pv; pv.x = acc[u][0]; pv.y = acc[u][1];
                *(ulonglong2*)&S.part2[sl2 * 384 + u * 96 + g2 * 4] = pv;
            }
        }
        __syncthreads();

        // ======== S4: combine2 + sigmoid (tid<192) ========
        if (tid < 192) {
            int ch = tid >> 1;
            int u  = ch / 24;
            int g  = ch - u * 24;
            int sp = tid & 1;
            int jj = 4 * g + u;
            int base = u * 96 + g * 4 + 2 * sp;
            u64 a = *(const u64*)&S.part2[base];
            #pragma unroll
            for (int q = 1; q < 16; q++)
                a = add2(a, *(const u64*)&S.part2[q * 384 + base]);
            float f0, f1; unpack2(a, f0, f1);
            if (jj < 9) {
                S.lgt[(2 * sp) * 12 + jj]     = f0;
                S.lgt[(2 * sp + 1) * 12 + jj] = f1;
            } else if (jj < 89) {
                S.outg[(2 * sp) * 80 + jj - 9]     = fast_sigmoid(f0);
                S.outg[(2 * sp + 1) * 80 + jj - 9] = fast_sigmoid(f1);
            }
        }
        __syncthreads();

        // ======== S5: epilogue (warps 0-3, warp s = sample s) ========
        if (warp < 4) {
            const int s = warp;
            float logit = (lane < 9) ? S.lgt[s * 12 + lane] : 0.f;
            float lg[9];
            #pragma unroll
            for (int k = 0; k < 9; k++)
                lg[k] = __shfl_sync(0xffffffffu, logit, k);
            __syncwarp();

            if (lane == 0) {
                float m01 = fmaxf(lg[0], lg[1]), m23 = fmaxf(lg[2], lg[3]);
                float m45 = fmaxf(lg[4], lg[5]), m67 = fmaxf(lg[6], lg[7]);
                float m = fmaxf(fmaxf(fmaxf(m01, m23), fmaxf(m45, m67)), lg[8]);
                float e[9];
                #pragma unroll
                for (int k = 0; k < 9; k++) e[k] = __expf(lg[k] - m);
                float s01 = e[0] + e[1], s23 = e[2] + e[3];
                float s45 = e[4] + e[5], s67 = e[6] + e[7];
                float ssum = ((s01 + s23) + (s45 + s67)) + e[8];
                float r2 = __fdividef(rain_cur, ssum);
                #pragma unroll
                for (int k = 0; k < 8; k++) sv[k] += e[k + 1] * r2;

                const float* bb = &S.outg[s * 80];
                #pragma unroll
                for (int d = 0; d < 8; d++) {
                    float4 bv0 = *(const float4*)&bb[d * 8];
                    float4 bv1 = *(const float4*)&bb[d * 8 + 4];
                    float fb0 = bv0.x * sv[0], fb1 = bv0.y * sv[1];
                    float fb2 = bv0.z * sv[2], fb3 = bv0.w * sv[3];
                    float fb4 = bv1.x * sv[4], fb5 = bv1.y * sv[5];
                    float fb6 = bv1.z * sv[6], fb7 = bv1.w * sv[7];
                    float fsum = ((fb0 + fb1) + (fb2 + fb3))
                               + ((fb4 + fb5) + (fb6 + fb7));
                    sv[0] -= fb0; sv[1] -= fb1; sv[2] -= fb2; sv[3] -= fb3;
                    sv[4] -= fb4; sv[5] -= fb5; sv[6] -= fb6; sv[7] -= fb7;
                    sv[d] += fsum;
                }
                {   // escape
                    float4 e0 = *(const float4*)&bb[64];
                    float4 e1 = *(const float4*)&bb[68];
                    sv[0] -= e0.x * sv[0]; sv[1] -= e0.y * sv[1];
                    sv[2] -= e0.z * sv[2]; sv[3] -= e0.w * sv[3];
                    sv[4] -= e1.x * sv[4]; sv[5] -= e1.y * sv[5];
                    sv[6] -= e1.z * sv[6]; sv[7] -= e1.w * sv[7];
                }
                {   // flow
                    float4 f0 = *(const float4*)&bb[72];
                    float4 f1 = *(const float4*)&bb[76];
                    float fd0 = f0.x * sv[0], fd1 = f0.y * sv[1];
                    float fd2 = f0.z * sv[2], fd3 = f0.w * sv[3];
                    float fd4 = f1.x * sv[4], fd5 = f1.y * sv[5];
                    float fd6 = f1.z * sv[6], fd7 = f1.w * sv[7];
                    float flow = ((fd0 + fd1) + (fd2 + fd3))
                               + ((fd4 + fd5) + (fd6 + fd7));
                    sv[0] -= fd0; sv[1] -= fd1; sv[2] -= fd2; sv[3] -= fd3;
                    sv[4] -= fd4; sv[5] -= fd5; sv[6] -= fd6; sv[7] -= fd7;
                    out[t * BATCH + bsample] = flow;
                    if (t == 0)
                        sv[2] = S.bflow_s[s] / fmaxf(f0.z, 1e-5f);  // b_flow[SLOW]
                }
                float4 o0 = make_float4(sv[0], sv[1], sv[2], sv[3]);
                float4 o1 = make_float4(sv[4], sv[5], sv[6], sv[7]);
                *(float4*)&S.st[s * 8]     = o0;
                *(float4*)&S.st[s * 8 + 4] = o1;
                rain_cur = rain_next;
            }
        }
        __syncthreads();

        // ======== S6: hA(t+1) finish (all 512) ========
        {
            int jj = tid >> 2, s = tid & 3;
            float4 s0 = *(const float4*)&S.st[s * 8];
            float4 s1 = *(const float4*)&S.st[s * 8 + 4];
            float v = S.l0p[jj * 4 + s];
            v = fmaf(w0spR[0], s0.x, v); v = fmaf(w0spR[1], s0.y, v);
            v = fmaf(w0spR[2], s0.z, v); v = fmaf(w0spR[3], s0.w, v);
            v = fmaf(w0spR[4], s1.x, v); v = fmaf(w0spR[5], s1.y, v);
            v = fmaf(w0spR[6], s1.z, v); v = fmaf(w0spR[7], s1.w, v);
            S.hA[jj * 4 + s] = fmaxf(v, 0.f);
        }
        __syncthreads();
    }
}

// ---------------------------------------------------------------------------
// Harness entry.  Inputs: hyd_input, W0, b0, W1, b1, W_in, b_in, W_out, b_out
// ---------------------------------------------------------------------------
extern "C" void kernel_launch(void* const* d_in, const int* in_sizes, int n_in,
                              void* d_out, int out_size) {
    const float* hyd = (const float*)d_in[0];
    const float* W0  = (const float*)d_in[1];
    const float* b0  = (const float*)d_in[2];
    const float* W1  = (const float*)d_in[3];
    const float* b1  = (const float*)d_in[4];
    const float* Wi  = (const float*)d_in[5];
    const float* bi  = (const float*)d_in[6];
    const float* Wo  = (const float*)d_in[7];
    const float* bo  = (const float*)d_in[8];
    float* out = (float*)d_out;

    cudaFuncSetAttribute(hyd_kernel,
                         cudaFuncAttributeMaxDynamicSharedMemorySize,
                         (int)sizeof(Smem));

    baseflow_kernel<<<BATCH, 1024>>>(hyd);
    hyd_kernel<<<NBLK, THREADS, sizeof(Smem)>>>(hyd, W0, b0, W1, b1, Wi, bi, Wo, bo, out);
}

// round 11
// speedup vs baseline: 1.3402x; 1.1704x over previous
#include <cuda_runtime.h>
#include <math.h>

#define STEPS 2048
#define BATCH 512
#define NBLK  128
#define THREADS 512

typedef unsigned long long u64;

__device__ float g_baseflow[BATCH];

// ---------------------------------------------------------------------------
__device__ __forceinline__ u64 pack2(float lo, float hi) {
    u64 r; asm("mov.b64 %0, {%1, %2};" : "=l"(r) : "f"(lo), "f"(hi)); return r;
}
__device__ __forceinline__ void fma2(u64& acc, u64 a, u64 b) {
    asm("fma.rn.f32x2 %0, %1, %2, %0;" : "+l"(acc) : "l"(a), "l"(b));
}
__device__ __forceinline__ float fast_sigmoid(float v) {
    return __fdividef(1.0f, 1.0f + __expf(-v));
}

// ---------------------------------------------------------------------------
// Kernel 1: per-batch-element 25th percentile of flow (bitonic sort)
// ---------------------------------------------------------------------------
__global__ void baseflow_kernel(const float* __restrict__ hyd) {
    __shared__ float v[STEPS];
    const int b = blockIdx.x;
    const int tid = threadIdx.x;
    for (int t = tid; t < STEPS; t += blockDim.x)
        v[t] = hyd[(t * BATCH + b) * 17];
    __syncthreads();
    for (int k = 2; k <= STEPS; k <<= 1) {
        for (int j = k >> 1; j > 0; j >>= 1) {
            for (int i = tid; i < STEPS; i += blockDim.x) {
                int l = i ^ j;
                if (l > i) {
                    float a = v[i], c = v[l];
                    bool up = ((i & k) == 0);
                    if ((a > c) == up) { v[i] = c; v[l] = a; }
                }
            }
            __syncthreads();
        }
    }
    if (tid == 0)
        g_baseflow[b] = 0.25f * v[511] + 0.75f * v[512];   // pos = 511.75
}

// ---------------------------------------------------------------------------
// SMEM (~32 KB, static)
// ---------------------------------------------------------------------------
struct __align__(16) Smem {
    float part1[4 * 512];    // [q][j][s] flat: q*512 + j*4 + s
    float part2[4 * 384];    // [q][j][s] flat: q*384 + j*4 + s (j padded to 96)
    float hA[512];           // [j][s]
    float hB[512];           // [j][s]
    float l0p[512];          // [j][s]  (layer0 x-part incl b0)
    float xin[64];           // [i][s]
    float outg[4 * 80];      // [s][col] sigmoided gates
    float lgt[4 * 16];       // [s][j] raw logits, padded to 16
    float st[32];            // [s][k] stores broadcast
    float bflow_s[4];
};

// ---------------------------------------------------------------------------
// 512 threads = 16 warps, 4 samples, one CTA/SM, one wave.
// j = tid&127 owns unit j; q = tid>>7 owns k-slice [32q, 32q+32).
// Stages (6 barriers):
//  S1: layer1 partials (R3 split-4 core) + LDG prefetch x/rain(t+1)
//  S2: combine1 -> hB (512 thr, coalesced flat adds) ; stage xin
//  S3: layer2 partials (j<89) || warps 3/7/11/15: l0x(t+1) -> l0p
//  S4: combine2 + sigmoid / logits (356 thr, coalesced)
//  S5: epilogue warps 0-3 (lane0 scalar softmax + mixing), publish st
//  S6: hA(t+1) = relu(l0p + 0.01*W0s . st)  (512 thr, coalesced)
// ---------------------------------------------------------------------------
__global__ void __launch_bounds__(THREADS, 1)
hyd_kernel(const float* __restrict__ hyd,
           const float* __restrict__ W0, const float* __restrict__ b0,
           const float* __restrict__ W1, const float* __restrict__ b1,
           const float* __restrict__ Wi, const float* __restrict__ bi,
           const float* __restrict__ Wo, const float* __restrict__ bo,
           float* __restrict__ out)
{
    __shared__ Smem S;
    const int tid  = threadIdx.x;
    const int j    = tid & 127;
    const int q    = tid >> 7;
    const int lane = tid & 31;
    const int warp = tid >> 5;
    const int blk  = blockIdx.x;

    // ---- register-resident weights / biases ----
    float w1r[32], wcr[32];
    float b1R = (q == 0) ? b1[j] : 0.f;
    float bcR = 0.f;
    #pragma unroll
    for (int k = 0; k < 32; k++) w1r[k] = W1[j * 128 + q * 32 + k];
    if (j < 9) {
        if (q == 0) bcR = bi[j];
        #pragma unroll
        for (int k = 0; k < 32; k++) wcr[k] = Wi[j * 128 + q * 32 + k];
    } else if (j < 89) {
        if (q == 0) bcR = bo[j - 9];
        #pragma unroll
        for (int k = 0; k < 32; k++) wcr[k] = Wo[(j - 9) * 128 + q * 32 + k];
    } else {
        #pragma unroll
        for (int k = 0; k < 32; k++) wcr[k] = 0.f;
    }
    // l0x role (warps 3/7/11/15): unit q*32+lane
    float w0tR[16], b0R = 0.f;
    if ((warp & 3) == 3) {
        int jj = q * 32 + lane;
        b0R = b0[jj];
        #pragma unroll
        for (int i = 0; i < 16; i++) w0tR[i] = W0[jj * 24 + i];
    }
    // hA-finish role (all): unit tid>>2
    float w0spR[8];
    {
        int jj = tid >> 2;
        #pragma unroll
        for (int k = 0; k < 8; k++) w0spR[k] = 0.01f * W0[jj * 24 + 16 + k];
    }

    // per-warp roles
    const int bsample = blk * 4 + warp;          // warps 0-3: epilogue sample
    const int xsample = blk * 4 + (warp - 8);    // warps 8-11: x prefetch
    float rain_cur = 0.f, rain_next = 0.f, xreg = 0.f;

    if (warp < 4 && lane == 0) rain_cur = hyd[bsample * 17 + 1];
    if (warp < 4 && lane < 4)  S.bflow_s[lane] = g_baseflow[blk * 4 + lane];
    if (warp >= 8 && warp < 12 && lane < 16)
        S.xin[lane * 4 + (warp - 8)] = hyd[xsample * 17 + 1 + lane];
    if (tid < 32) S.st[tid] = ((tid & 7) == 1) ? 1.0f : 0.0f;
    __syncthreads();

    // ---- bootstrap: l0p(0) ----
    if ((warp & 3) == 3) {
        int jj = q * 32 + lane;
        u64 a01 = pack2(b0R, b0R), a23 = a01;
        #pragma unroll
        for (int i = 0; i < 16; i++) {
            ulonglong2 h = *(const ulonglong2*)&S.xin[i * 4];
            u64 wd = pack2(w0tR[i], w0tR[i]);
            fma2(a01, h.x, wd); fma2(a23, h.y, wd);
        }
        ulonglong2 pv; pv.x = a01; pv.y = a23;
        *(ulonglong2*)&S.l0p[jj * 4] = pv;
    }
    __syncthreads();
    // ---- bootstrap: hA(0) ----
    {
        int s = tid & 3;
        float4 s0 = *(const float4*)&S.st[s * 8];
        float4 s1 = *(const float4*)&S.st[s * 8 + 4];
        float v = S.l0p[tid];
        v = fmaf(w0spR[0], s0.x, v); v = fmaf(w0spR[1], s0.y, v);
        v = fmaf(w0spR[2], s0.z, v); v = fmaf(w0spR[3], s0.w, v);
        v = fmaf(w0spR[4], s1.x, v); v = fmaf(w0spR[5], s1.y, v);
        v = fmaf(w0spR[6], s1.z, v); v = fmaf(w0spR[7], s1.w, v);
        S.hA[tid] = fmaxf(v, 0.f);
    }
    __syncthreads();

    // persistent stores in lane 0 of warps 0-3
    float sv[8];
    #pragma unroll
    for (int k = 0; k < 8; k++) sv[k] = (k == 1) ? 1.0f : 0.0f;

    for (int t = 0; t < STEPS; t++) {
        // ======== S1: layer1 partials (+ prefetch) ========
        if (t + 1 < STEPS) {
            if (warp < 4 && lane == 0)
                rain_next = hyd[((t + 1) * BATCH + bsample) * 17 + 1];
            if (warp >= 8 && warp < 12 && lane < 16)
                xreg = hyd[((t + 1) * BATCH + xsample) * 17 + 1 + lane];
        }
        {
            u64 a01 = pack2(b1R, b1R), a23 = a01;
            const float* hp = &S.hA[q * 128];
            #pragma unroll
            for (int k = 0; k < 32; k++) {
                u64 wd = pack2(w1r[k], w1r[k]);
                ulonglong2 h = *(const ulonglong2*)&hp[k * 4];
                fma2(a01, h.x, wd); fma2(a23, h.y, wd);
            }
            ulonglong2 pv; pv.x = a01; pv.y = a23;
            *(ulonglong2*)&S.part1[q * 512 + j * 4] = pv;
        }
        __syncthreads();

        // ======== S2: combine1 -> hB (coalesced flat) ; stage xin ========
        {
            float v = S.part1[tid]        + S.part1[512 + tid]
                    + S.part1[1024 + tid] + S.part1[1536 + tid];
            S.hB[tid] = fmaxf(v, 0.f);
        }
        if (warp >= 8 && warp < 12 && lane < 16)
            S.xin[lane * 4 + (warp - 8)] = xreg;
        __syncthreads();

        // ======== S3: layer2 partials || l0x(t+1) ========
        if ((warp & 3) == 3) {
            int jj = q * 32 + lane;
            u64 a01 = pack2(b0R, b0R), a23 = a01;
            #pragma unroll
            for (int i = 0; i < 16; i++) {
                ulonglong2 h = *(const ulonglong2*)&S.xin[i * 4];
                u64 wd = pack2(w0tR[i], w0tR[i]);
                fma2(a01, h.x, wd); fma2(a23, h.y, wd);
            }
            ulonglong2 pv; pv.x = a01; pv.y = a23;
            *(ulonglong2*)&S.l0p[jj * 4] = pv;
        } else if (j < 89) {
            u64 a01 = pack2(bcR, bcR), a23 = a01;
            const float* hp = &S.hB[q * 128];
            #pragma unroll
            for (int k = 0; k < 32; k++) {
                u64 wd = pack2(wcr[k], wcr[k]);
                ulonglong2 h = *(const ulonglong2*)&hp[k * 4];
                fma2(a01, h.x, wd); fma2(a23, h.y, wd);
            }
            ulonglong2 pv; pv.x = a01; pv.y = a23;
            *(ulonglong2*)&S.part2[q * 384 + j * 4] = pv;
        }
        __syncthreads();

        // ======== S4: combine2 + sigmoid / logits (356 thr, coalesced) ====
        if (tid < 356) {
            int jj = tid >> 2, s = tid & 3;
            float v = S.part2[tid]        + S.part2[384 + tid]
                    + S.part2[768 + tid]  + S.part2[1152 + tid];
            if (jj < 9) S.lgt[s * 16 + jj] = v;
            else        S.outg[s * 80 + jj - 9] = fast_sigmoid(v);
        }
        __syncthreads();

        // ======== S5: epilogue (warps 0-3, lane 0 scalar) ========
        if (warp < 4 && lane == 0) {
            const int s = warp;
            float4 la = *(const float4*)&S.lgt[s * 16];
            float4 lb = *(const float4*)&S.lgt[s * 16 + 4];
            float  l8 = S.lgt[s * 16 + 8];
            float m01 = fmaxf(la.x, la.y), m23 = fmaxf(la.z, la.w);
            float m45 = fmaxf(lb.x, lb.y), m67 = fmaxf(lb.z, lb.w);
            float m = fmaxf(fmaxf(fmaxf(m01, m23), fmaxf(m45, m67)), l8);
            float e0 = __expf(la.x - m), e1 = __expf(la.y - m);
            float e2 = __expf(la.z - m), e3 = __expf(la.w - m);
            float e4 = __expf(lb.x - m), e5 = __expf(lb.y - m);
            float e6 = __expf(lb.z - m), e7 = __expf(lb.w - m);
            float e8 = __expf(l8 - m);
            float ssum = (((e0 + e1) + (e2 + e3)) + ((e4 + e5) + (e6 + e7))) + e8;
            float r2 = __fdividef(rain_cur, ssum);
            sv[0] += e1 * r2; sv[1] += e2 * r2; sv[2] += e3 * r2; sv[3] += e4 * r2;
            sv[4] += e5 * r2; sv[5] += e6 * r2; sv[6] += e7 * r2; sv[7] += e8 * r2;

            const float* bb = &S.outg[s * 80];
            #pragma unroll
            for (int d = 0; d < 8; d++) {
                float4 bv0 = *(const float4*)&bb[d * 8];
                float4 bv1 = *(const float4*)&bb[d * 8 + 4];
                float fb0 = bv0.x * sv[0], fb1 = bv0.y * sv[1];
                float fb2 = bv0.z * sv[2], fb3 = bv0.w * sv[3];
                float fb4 = bv1.x * sv[4], fb5 = bv1.y * sv[5];
                float fb6 = bv1.z * sv[6], fb7 = bv1.w * sv[7];
                float fsum = ((fb0 + fb1) + (fb2 + fb3))
                           + ((fb4 + fb5) + (fb6 + fb7));
                sv[0] -= fb0; sv[1] -= fb1; sv[2] -= fb2; sv[3] -= fb3;
                sv[4] -= fb4; sv[5] -= fb5; sv[6] -= fb6; sv[7] -= fb7;
                sv[d] += fsum;
            }
            {   // escape
                float4 ea = *(const float4*)&bb[64];
                float4 eb = *(const float4*)&bb[68];
                sv[0] -= ea.x * sv[0]; sv[1] -= ea.y * sv[1];
                sv[2] -= ea.z * sv[2]; sv[3] -= ea.w * sv[3];
                sv[4] -= eb.x * sv[4]; sv[5] -= eb.y * sv[5];
                sv[6] -= eb.z * sv[6]; sv[7] -= eb.w * sv[7];
            }
            {   // flow distn
                float4 f0 = *(const float4*)&bb[72];
                float4 f1 = *(const float4*)&bb[76];
                float fd0 = f0.x * sv[0], fd1 = f0.y * sv[1];
                float fd2 = f0.z * sv[2], fd3 = f0.w * sv[3];
                float fd4 = f1.x * sv[4], fd5 = f1.y * sv[5];
                float fd6 = f1.z * sv[6], fd7 = f1.w * sv[7];
                float flow = ((fd0 + fd1) + (fd2 + fd3))
                           + ((fd4 + fd5) + (fd6 + fd7));
                sv[0] -= fd0; sv[1] -= fd1; sv[2] -= fd2; sv[3] -= fd3;
                sv[4] -= fd4; sv[5] -= fd5; sv[6] -= fd6; sv[7] -= fd7;
                out[t * BATCH + bsample] = flow;
                if (t == 0)
                    sv[2] = S.bflow_s[s] / fmaxf(f0.z, 1e-5f);   // b_flow[SLOW]
            }
            *(float4*)&S.st[s * 8]     = make_float4(sv[0], sv[1], sv[2], sv[3]);
            *(float4*)&S.st[s * 8 + 4] = make_float4(sv[4], sv[5], sv[6], sv[7]);
            rain_cur = rain_next;
        }
        __syncthreads();

        // ======== S6: hA(t+1) finish (512 thr, coalesced) ========
        {
            int s = tid & 3;
            float4 s0 = *(const float4*)&S.st[s * 8];
            float4 s1 = *(const float4*)&S.st[s * 8 + 4];
            float v = S.l0p[tid];
            v = fmaf(w0spR[0], s0.x, v); v = fmaf(w0spR[1], s0.y, v);
            v = fmaf(w0spR[2], s0.z, v); v = fmaf(w0spR[3], s0.w, v);
            v = fmaf(w0spR[4], s1.x, v); v = fmaf(w0spR[5], s1.y, v);
            v = fmaf(w0spR[6], s1.z, v); v = fmaf(w0spR[7], s1.w, v);
            S.hA[tid] = fmaxf(v, 0.f);
        }
        __syncthreads();
    }
}

// ---------------------------------------------------------------------------
// Harness entry.  Inputs: hyd_input, W0, b0, W1, b1, W_in, b_in, W_out, b_out
// ---------------------------------------------------------------------------
extern "C" void kernel_launch(void* const* d_in, const int* in_sizes, int n_in,
                              void* d_out, int out_size) {
    const float* hyd = (const float*)d_in[0];
    const float* W0  = (const float*)d_in[1];
    const float* b0  = (const float*)d_in[2];
    const float* W1  = (const float*)d_in[3];
    const float* b1  = (const float*)d_in[4];
    const float* Wi  = (const float*)d_in[5];
    const float* bi  = (const float*)d_in[6];
    const float* Wo  = (const float*)d_in[7];
    const float* bo  = (const float*)d_in[8];
    float* out = (float*)d_out;

    baseflow_kernel<<<BATCH, 1024>>>(hyd);
    hyd_kernel<<<NBLK, THREADS>>>(hyd, W0, b0, W1, b1, Wi, bi, Wo, bo, out);
}